// round 1
// baseline (speedup 1.0000x reference)
#include <cuda_runtime.h>

// ---------------- problem constants ----------------
#define BSZ   4096
#define MAXN  10
#define NVT   26
#define MAXPOS 9
#define HS    301
#define NZ    56
#define EMB   16
#define FEAT  8
#define VS    310       // HS + MAXPOS
#define XDIM  35        // NVT + MAXPOS
#define DFD   27        // 3*MAXPOS
#define GS    309       // HS + FEAT

// ---------------- scratch (device globals: no allocation allowed) ----------------
__device__ float g_gated[(size_t)9 * BSZ * HS];   // gated[u] for u=0..8
__device__ float g_Hin[(size_t)BSZ * HS];
__device__ float g_Hv [(size_t)BSZ * HS];
__device__ float g_Hg [(size_t)BSZ * HS];
__device__ float g_Hd [(size_t)BSZ * FEAT];
__device__ int   g_n  [BSZ];

__device__ __forceinline__ float sigm(float x) { return 1.f / (1.f + __expf(-x)); }

// ---------------- setup: n clip, df features, df_enc MLP ----------------
__global__ void setup_kernel(const int* __restrict__ vc, const int* __restrict__ pos,
                             const float* __restrict__ r, const float* __restrict__ c_,
                             const float* __restrict__ gm,
                             const float* __restrict__ W1, const float* __restrict__ b1,
                             const float* __restrict__ W2, const float* __restrict__ b2)
{
    int b = blockIdx.x * blockDim.x + threadIdx.x;
    if (b >= BSZ) return;
    int nb = vc[b]; nb = nb < 1 ? 1 : (nb > MAXN ? MAXN : nb);
    g_n[b] = nb;

    float df[DFD];
#pragma unroll
    for (int d = 0; d < DFD; ++d) df[d] = 0.f;
    for (int v = 0; v < MAXN; ++v) {
        if (v < nb) {
            int p = pos[b * MAXN + v] * 3;
            df[p]     = r [b * MAXN + v];
            df[p + 1] = c_[b * MAXN + v];
            df[p + 2] = gm[b * MAXN + v];
        }
    }
    float t16[EMB];
#pragma unroll
    for (int e = 0; e < EMB; ++e) {
        float s = b1[e];
#pragma unroll
        for (int d = 0; d < DFD; ++d) s += df[d] * W1[e * DFD + d];
        t16[e] = fmaxf(s, 0.f);
    }
#pragma unroll
    for (int f = 0; f < FEAT; ++f) {
        float s = b2[f];
#pragma unroll
        for (int e = 0; e < EMB; ++e) s += t16[e] * W2[f * EMB + e];
        g_Hd[b * FEAT + f] = s;
    }
}

// ---------------- predecessor aggregation: Hin[b,:] = sum_{u<v} A[b,u,v]*gated[u][b,:] ----------------
__global__ void agg_kernel(const int* __restrict__ adj, int v)
{
    int b = blockIdx.x;
    int k = threadIdx.x;
    if (k >= HS) return;
    int nb = g_n[b];
    float s = 0.f;
    if (v < nb) {
        for (int u = 0; u < v; ++u) {              // u < v < nb  => u valid
            int a = adj[(size_t)b * MAXN * MAXN + u * MAXN + v];
            if (a) s += g_gated[((size_t)u * BSZ + b) * HS + k];
        }
    }
    g_Hin[(size_t)b * HS + k] = s;
}

// ---------------- GRU step: gh GEMM (3 gangs of N=301, K=301) + fused GRU epilogue ----------------
// block tile: 64 batch rows x 64 h cols (x3 gates). 256 threads, 8 outputs x 2 cols x 3 gates each.
#define BKK 16
__global__ void __launch_bounds__(256, 2) gru_step_kernel(
    const float* __restrict__ Whh, const float* __restrict__ Wih,
    const float* __restrict__ bih, const float* __restrict__ bhh,
    const int* __restrict__ node_type, const int* __restrict__ pos,
    int v, int has_agg)
{
    __shared__ __align__(16) float As[BKK][64 + 4];
    __shared__ __align__(16) float Bs[3][BKK][64 + 4];
    const int tid = threadIdx.x;
    const int tx = tid & 31;
    const int ty = tid >> 5;
    const int bn = blockIdx.x * 64;   // h tile
    const int bm = blockIdx.y * 64;   // batch tile

    float acc[3][2][8];
#pragma unroll
    for (int g = 0; g < 3; ++g)
#pragma unroll
        for (int c = 0; c < 2; ++c)
#pragma unroll
            for (int i = 0; i < 8; ++i) acc[g][c][i] = 0.f;

    if (has_agg) {
        const int NT = (HS + BKK - 1) / BKK;   // 19
        const int lm = tid >> 2;               // 0..63
        const int lk = (tid & 3) * 4;          // 0,4,8,12
        const int brow = bn + lm;
        const float* Ar = g_Hin + (size_t)(bm + lm) * HS;

        float a_st[4], b_st[3][4];
        // stage tile 0
        {
#pragma unroll
            for (int j = 0; j < 4; ++j) { int k = lk + j; a_st[j] = (k < HS) ? Ar[k] : 0.f; }
#pragma unroll
            for (int g = 0; g < 3; ++g) {
                const float* Br = Whh + ((size_t)(brow + g * HS)) * HS;
#pragma unroll
                for (int j = 0; j < 4; ++j) {
                    int k = lk + j;
                    b_st[g][j] = (brow < HS && k < HS) ? Br[k] : 0.f;
                }
            }
        }
        for (int kt = 0; kt < NT; ++kt) {
            __syncthreads();
#pragma unroll
            for (int j = 0; j < 4; ++j) As[lk + j][lm] = a_st[j];
#pragma unroll
            for (int g = 0; g < 3; ++g)
#pragma unroll
                for (int j = 0; j < 4; ++j) Bs[g][lk + j][lm] = b_st[g][j];
            __syncthreads();
            if (kt + 1 < NT) {
                int k0 = (kt + 1) * BKK;
#pragma unroll
                for (int j = 0; j < 4; ++j) { int k = k0 + lk + j; a_st[j] = (k < HS) ? Ar[k] : 0.f; }
#pragma unroll
                for (int g = 0; g < 3; ++g) {
                    const float* Br = Whh + ((size_t)(brow + g * HS)) * HS;
#pragma unroll
                    for (int j = 0; j < 4; ++j) {
                        int k = k0 + lk + j;
                        b_st[g][j] = (brow < HS && k < HS) ? Br[k] : 0.f;
                    }
                }
            }
#pragma unroll
            for (int kk = 0; kk < BKK; ++kk) {
                float4 a0 = *(const float4*)&As[kk][ty * 8];
                float4 a1 = *(const float4*)&As[kk][ty * 8 + 4];
                float av[8] = {a0.x, a0.y, a0.z, a0.w, a1.x, a1.y, a1.z, a1.w};
#pragma unroll
                for (int g = 0; g < 3; ++g) {
                    float b0 = Bs[g][kk][tx];
                    float b1 = Bs[g][kk][tx + 32];
#pragma unroll
                    for (int i = 0; i < 8; ++i) {
                        acc[g][0][i] += av[i] * b0;
                        acc[g][1][i] += av[i] * b1;
                    }
                }
            }
        }
    }

    // fused GRU epilogue (gi via one-hot column gathers)
#pragma unroll
    for (int i = 0; i < 8; ++i) {
        int b = bm + ty * 8 + i;
        int nt = node_type[b * MAXN + v];
        int pv = pos[b * MAXN + v];
        int nb = g_n[b];
        bool valid = (v < nb);
#pragma unroll
        for (int c = 0; c < 2; ++c) {
            int h = bn + tx + c * 32;
            if (h >= HS) continue;
            float gir = Wih[h * XDIM + nt]            + Wih[h * XDIM + NVT + pv]            + bih[h];
            float giz = Wih[(h + HS) * XDIM + nt]     + Wih[(h + HS) * XDIM + NVT + pv]     + bih[h + HS];
            float gin = Wih[(h + 2 * HS) * XDIM + nt] + Wih[(h + 2 * HS) * XDIM + NVT + pv] + bih[h + 2 * HS];
            float hin = has_agg ? g_Hin[(size_t)b * HS + h] : 0.f;
            float rg = sigm(gir + acc[0][c][i] + bhh[h]);
            float zg = sigm(giz + acc[1][c][i] + bhh[h + HS]);
            float ng = tanhf(gin + rg * (acc[2][c][i] + bhh[h + 2 * HS]));
            float hv = (1.f - zg) * ng + zg * hin;
            hv = valid ? hv : 0.f;
            g_Hv[(size_t)b * HS + h] = hv;
            if (v == nb - 1) g_Hg[(size_t)b * HS + h] = hv;
        }
    }
}

// ---------------- gate/mapper step: 2-gang GEMM (K=301) + fused sigmoid*mapper epilogue ----------------
__global__ void __launch_bounds__(256, 2) gate_step_kernel(
    const float* __restrict__ Wg, const float* __restrict__ bg,
    const float* __restrict__ Wm,
    const int* __restrict__ pos, int v)
{
    __shared__ __align__(16) float As[BKK][64 + 4];
    __shared__ __align__(16) float Bs[2][BKK][64 + 4];
    const int tid = threadIdx.x;
    const int tx = tid & 31;
    const int ty = tid >> 5;
    const int bn = blockIdx.x * 64;
    const int bm = blockIdx.y * 64;

    float acc[2][2][8];
#pragma unroll
    for (int g = 0; g < 2; ++g)
#pragma unroll
        for (int c = 0; c < 2; ++c)
#pragma unroll
            for (int i = 0; i < 8; ++i) acc[g][c][i] = 0.f;

    const int NT = (HS + BKK - 1) / BKK;
    const int lm = tid >> 2;
    const int lk = (tid & 3) * 4;
    const int brow = bn + lm;
    const float* Ar = g_Hv + (size_t)(bm + lm) * HS;
    const float* Bbase[2] = {Wg, Wm};

    float a_st[4], b_st[2][4];
    {
#pragma unroll
        for (int j = 0; j < 4; ++j) { int k = lk + j; a_st[j] = (k < HS) ? Ar[k] : 0.f; }
#pragma unroll
        for (int g = 0; g < 2; ++g) {
            const float* Br = Bbase[g] + (size_t)brow * VS;
#pragma unroll
            for (int j = 0; j < 4; ++j) {
                int k = lk + j;
                b_st[g][j] = (brow < HS && k < HS) ? Br[k] : 0.f;
            }
        }
    }
    for (int kt = 0; kt < NT; ++kt) {
        __syncthreads();
#pragma unroll
        for (int j = 0; j < 4; ++j) As[lk + j][lm] = a_st[j];
#pragma unroll
        for (int g = 0; g < 2; ++g)
#pragma unroll
            for (int j = 0; j < 4; ++j) Bs[g][lk + j][lm] = b_st[g][j];
        __syncthreads();
        if (kt + 1 < NT) {
            int k0 = (kt + 1) * BKK;
#pragma unroll
            for (int j = 0; j < 4; ++j) { int k = k0 + lk + j; a_st[j] = (k < HS) ? Ar[k] : 0.f; }
#pragma unroll
            for (int g = 0; g < 2; ++g) {
                const float* Br = Bbase[g] + (size_t)brow * VS;
#pragma unroll
                for (int j = 0; j < 4; ++j) {
                    int k = k0 + lk + j;
                    b_st[g][j] = (brow < HS && k < HS) ? Br[k] : 0.f;
                }
            }
        }
#pragma unroll
        for (int kk = 0; kk < BKK; ++kk) {
            float4 a0 = *(const float4*)&As[kk][ty * 8];
            float4 a1 = *(const float4*)&As[kk][ty * 8 + 4];
            float av[8] = {a0.x, a0.y, a0.z, a0.w, a1.x, a1.y, a1.z, a1.w};
#pragma unroll
            for (int g = 0; g < 2; ++g) {
                float b0 = Bs[g][kk][tx];
                float b1 = Bs[g][kk][tx + 32];
#pragma unroll
                for (int i = 0; i < 8; ++i) {
                    acc[g][0][i] += av[i] * b0;
                    acc[g][1][i] += av[i] * b1;
                }
            }
        }
    }

#pragma unroll
    for (int i = 0; i < 8; ++i) {
        int b = bm + ty * 8 + i;
        int pv = pos[b * MAXN + v];
#pragma unroll
        for (int c = 0; c < 2; ++c) {
            int j = bn + tx + c * 32;
            if (j >= HS) continue;
            float gg = sigm(acc[0][c][i] + bg[j] + Wg[j * VS + HS + pv]);
            float mm = acc[1][c][i] + Wm[j * VS + HS + pv];
            g_gated[((size_t)v * BSZ + b) * HS + j] = gg * mm;
        }
    }
}

// ---------------- heads: mu / logvar over Hfull = [Hg, Hd] ----------------
__global__ void final_kernel(const float* __restrict__ Wmu, const float* __restrict__ bmu,
                             const float* __restrict__ Wlv, const float* __restrict__ blv,
                             float* __restrict__ out)
{
    __shared__ float sh[8][GS + 3];
    int b0 = blockIdx.x * 8;
    for (int idx = threadIdx.x; idx < 8 * HS; idx += blockDim.x) {
        int i = idx / HS, k = idx % HS;
        sh[i][k] = g_Hg[(size_t)(b0 + i) * HS + k];
    }
    for (int idx = threadIdx.x; idx < 8 * FEAT; idx += blockDim.x) {
        int i = idx / FEAT, f = idx % FEAT;
        sh[i][HS + f] = g_Hd[(b0 + i) * FEAT + f];
    }
    __syncthreads();
    int t = threadIdx.x;
    if (t < 2 * NZ) {
        int head = t / NZ;
        int o = t % NZ;
        const float* W = head ? Wlv : Wmu;
        float bias = head ? blv[o] : bmu[o];
        float acc[8];
#pragma unroll
        for (int i = 0; i < 8; ++i) acc[i] = 0.f;
        for (int k = 0; k < GS; ++k) {
            float wv = W[o * GS + k];
#pragma unroll
            for (int i = 0; i < 8; ++i) acc[i] += sh[i][k] * wv;
        }
#pragma unroll
        for (int i = 0; i < 8; ++i)
            out[(size_t)head * BSZ * NZ + (size_t)(b0 + i) * NZ + o] = acc[i] + bias;
    }
}

// ---------------- launch ----------------
extern "C" void kernel_launch(void* const* d_in, const int* in_sizes, int n_in,
                              void* d_out, int out_size)
{
    const int*   node_type = (const int*)  d_in[0];
    const int*   pos       = (const int*)  d_in[1];
    const int*   adj       = (const int*)  d_in[2];
    const int*   vcount    = (const int*)  d_in[3];
    const float* r         = (const float*)d_in[4];
    const float* c         = (const float*)d_in[5];
    const float* gm        = (const float*)d_in[6];
    const float* Wih       = (const float*)d_in[7];
    const float* Whh       = (const float*)d_in[8];
    const float* bih       = (const float*)d_in[9];
    const float* bhh       = (const float*)d_in[10];
    const float* Wg        = (const float*)d_in[11];
    const float* bg        = (const float*)d_in[12];
    const float* Wm        = (const float*)d_in[13];
    const float* W1        = (const float*)d_in[14];
    const float* b1        = (const float*)d_in[15];
    const float* W2        = (const float*)d_in[16];
    const float* b2        = (const float*)d_in[17];
    const float* Wmu       = (const float*)d_in[18];
    const float* bmu       = (const float*)d_in[19];
    const float* Wlv       = (const float*)d_in[20];
    const float* blv       = (const float*)d_in[21];
    float* out = (float*)d_out;

    setup_kernel<<<BSZ / 128, 128>>>(vcount, pos, r, c, gm, W1, b1, W2, b2);

    dim3 gemm_grid((HS + 63) / 64, BSZ / 64);   // (5, 64)
    for (int v = 0; v < MAXN; ++v) {
        if (v > 0) agg_kernel<<<BSZ, 320>>>(adj, v);
        gru_step_kernel<<<gemm_grid, 256>>>(Whh, Wih, bih, bhh, node_type, pos, v, v > 0 ? 1 : 0);
        if (v < MAXN - 1) gate_step_kernel<<<gemm_grid, 256>>>(Wg, bg, Wm, pos, v);
    }
    final_kernel<<<BSZ / 8, 128>>>(Wmu, bmu, Wlv, blv, out);
}

// round 2
// speedup vs baseline: 2.1194x; 2.1194x over previous
#include <cuda_runtime.h>
#include <cstdint>

// ---------------- problem constants ----------------
#define BSZ   4096
#define MAXN  10
#define NVT   26
#define MAXPOS 9
#define HS    301
#define NZ    56
#define EMB   16
#define FEAT  8
#define VS    310       // HS + MAXPOS
#define XDIM  35        // NVT + MAXPOS
#define DFD   27        // 3*MAXPOS
#define GS    309       // HS + FEAT

#define KP    304       // K padded (19*16)
#define NPG   320       // per-gang N padded
#define NG_GRU  (3*NPG) // 960
#define NG_GATE (2*NPG) // 640

// ---------------- scratch (device globals; zero-initialized, pads never written) ----------------
__device__ float g_gated[(size_t)9 * BSZ * KP];   // gated[u], padded cols 301..303 stay 0
__device__ float g_Hin[(size_t)BSZ * KP];         // padded
__device__ float g_Hv [(size_t)BSZ * KP];         // padded
__device__ float g_Hg [(size_t)BSZ * HS];
__device__ float g_Hd [(size_t)BSZ * FEAT];
__device__ int   g_n  [BSZ];
__device__ unsigned g_pmask[(size_t)BSZ * MAXN];
__device__ float g_GEMM[(size_t)BSZ * NG_GRU];    // GEMM output scratch (reused)
__device__ float g_Whh_p[(size_t)NG_GRU * KP];    // packed padded Whh (3 gangs of 320)
__device__ float g_Wgm_p[(size_t)NG_GATE * KP];   // packed padded Wg|Wm

__device__ __forceinline__ float sigm(float x) { return 1.f / (1.f + __expf(-x)); }
__device__ __forceinline__ float f2tf(float x) {
    uint32_t r; asm("cvt.rna.tf32.f32 %0, %1;" : "=r"(r) : "f"(x)); return __uint_as_float(r);
}

// ---------------- setup: n clip, pred bitmasks, df features, df_enc MLP ----------------
__global__ void setup_kernel(const int* __restrict__ vc, const int* __restrict__ pos,
                             const int* __restrict__ adj,
                             const float* __restrict__ r, const float* __restrict__ c_,
                             const float* __restrict__ gm,
                             const float* __restrict__ W1, const float* __restrict__ b1,
                             const float* __restrict__ W2, const float* __restrict__ b2)
{
    int b = blockIdx.x * blockDim.x + threadIdx.x;
    if (b >= BSZ) return;
    int nb = vc[b]; nb = nb < 1 ? 1 : (nb > MAXN ? MAXN : nb);
    g_n[b] = nb;

    // predecessor bitmasks: bit u of pmask[b][v] set iff u<v<nb and adj[b][u][v]
    for (int v = 0; v < MAXN; ++v) {
        unsigned m = 0;
        if (v < nb)
            for (int u = 0; u < v; ++u)
                if (adj[(size_t)b * 100 + u * 10 + v]) m |= 1u << u;
        g_pmask[b * MAXN + v] = m;
    }

    float df[DFD];
#pragma unroll
    for (int d = 0; d < DFD; ++d) df[d] = 0.f;
    for (int v = 0; v < MAXN; ++v) {
        if (v < nb) {
            int p = pos[b * MAXN + v] * 3;
            df[p]     = r [b * MAXN + v];
            df[p + 1] = c_[b * MAXN + v];
            df[p + 2] = gm[b * MAXN + v];
        }
    }
    float t16[EMB];
#pragma unroll
    for (int e = 0; e < EMB; ++e) {
        float s = b1[e];
#pragma unroll
        for (int d = 0; d < DFD; ++d) s += df[d] * W1[e * DFD + d];
        t16[e] = fmaxf(s, 0.f);
    }
#pragma unroll
    for (int f = 0; f < FEAT; ++f) {
        float s = b2[f];
#pragma unroll
        for (int e = 0; e < EMB; ++e) s += t16[e] * W2[f * EMB + e];
        g_Hd[b * FEAT + f] = s;
    }
}

// ---------------- weight packing: zero-padded [gang*320+n][304] ----------------
__global__ void pack_kernel(const float* __restrict__ Whh,
                            const float* __restrict__ Wg, const float* __restrict__ Wm)
{
    int idx = blockIdx.x * blockDim.x + threadIdx.x;
    int tot1 = NG_GRU * KP;
    int tot2 = NG_GATE * KP;
    if (idx < tot1) {
        int row = idx / KP, k = idx % KP;
        int gg = row / NPG, n = row % NPG;
        float v = 0.f;
        if (n < HS && k < HS) v = Whh[(size_t)(gg * HS + n) * HS + k];
        g_Whh_p[idx] = v;
    } else if (idx < tot1 + tot2) {
        int j = idx - tot1;
        int row = j / KP, k = j % KP;
        int gg = row / NPG, n = row % NPG;
        const float* src = gg ? Wm : Wg;
        float v = 0.f;
        if (n < HS && k < HS) v = src[(size_t)n * VS + k];
        g_Wgm_p[j] = v;
    }
}

// ---------------- generic tf32 tensor-core GEMM: C[4096 x Ng] = A[4096 x 304] * B[Ng x 304]^T ----
// BM=128, BN=64, BK=16, 256 threads (8 warps: 4 m x 2 n), warp tile 32x32, mma m16n8k8
__global__ void __launch_bounds__(256) gemm_tf32(const float* __restrict__ A,
                                                 const float* __restrict__ B,
                                                 float* __restrict__ C, int ldc)
{
    __shared__ float As[128][20];
    __shared__ float Bs[64][20];
    const int tid  = threadIdx.x;
    const int warp = tid >> 5, lane = tid & 31;
    const int wm = warp & 3, wn = warp >> 2;
    const int g  = lane >> 2, tg = lane & 3;
    const int bm = blockIdx.x * 128, bn = blockIdx.y * 64;

    float c[2][4][4];
#pragma unroll
    for (int mi = 0; mi < 2; ++mi)
#pragma unroll
        for (int ni = 0; ni < 4; ++ni)
#pragma unroll
            for (int q = 0; q < 4; ++q) c[mi][ni][q] = 0.f;

    const int ar0 = tid >> 2, ac = (tid & 3) * 4;   // A: two rows per thread (ar0, ar0+64)
    const int br  = tid >> 2;                       // B: one row per thread

    for (int kt = 0; kt < KP / 16; ++kt) {
        const int k0g = kt * 16;
        float4 a0 = *(const float4*)(A + (size_t)(bm + ar0) * KP + k0g + ac);
        float4 a1 = *(const float4*)(A + (size_t)(bm + ar0 + 64) * KP + k0g + ac);
        float4 bv = *(const float4*)(B + (size_t)(bn + br) * KP + k0g + ac);
        __syncthreads();
        As[ar0][ac]          = f2tf(a0.x); As[ar0][ac + 1]      = f2tf(a0.y);
        As[ar0][ac + 2]      = f2tf(a0.z); As[ar0][ac + 3]      = f2tf(a0.w);
        As[ar0 + 64][ac]     = f2tf(a1.x); As[ar0 + 64][ac + 1] = f2tf(a1.y);
        As[ar0 + 64][ac + 2] = f2tf(a1.z); As[ar0 + 64][ac + 3] = f2tf(a1.w);
        Bs[br][ac]     = f2tf(bv.x); Bs[br][ac + 1] = f2tf(bv.y);
        Bs[br][ac + 2] = f2tf(bv.z); Bs[br][ac + 3] = f2tf(bv.w);
        __syncthreads();
#pragma unroll
        for (int ks = 0; ks < 2; ++ks) {
            const int k0 = ks * 8;
            uint32_t af[2][4];
#pragma unroll
            for (int mi = 0; mi < 2; ++mi) {
                int rb = wm * 32 + mi * 16;
                af[mi][0] = __float_as_uint(As[rb + g    ][k0 + tg]);
                af[mi][1] = __float_as_uint(As[rb + g + 8][k0 + tg]);
                af[mi][2] = __float_as_uint(As[rb + g    ][k0 + tg + 4]);
                af[mi][3] = __float_as_uint(As[rb + g + 8][k0 + tg + 4]);
            }
            uint32_t bf[4][2];
#pragma unroll
            for (int ni = 0; ni < 4; ++ni) {
                int nb0 = wn * 32 + ni * 8;
                bf[ni][0] = __float_as_uint(Bs[nb0 + g][k0 + tg]);
                bf[ni][1] = __float_as_uint(Bs[nb0 + g][k0 + tg + 4]);
            }
#pragma unroll
            for (int mi = 0; mi < 2; ++mi)
#pragma unroll
                for (int ni = 0; ni < 4; ++ni) {
                    asm volatile(
                        "mma.sync.aligned.m16n8k8.row.col.f32.tf32.tf32.f32 "
                        "{%0,%1,%2,%3}, {%4,%5,%6,%7}, {%8,%9}, {%0,%1,%2,%3};"
                        : "+f"(c[mi][ni][0]), "+f"(c[mi][ni][1]),
                          "+f"(c[mi][ni][2]), "+f"(c[mi][ni][3])
                        : "r"(af[mi][0]), "r"(af[mi][1]), "r"(af[mi][2]), "r"(af[mi][3]),
                          "r"(bf[ni][0]), "r"(bf[ni][1]));
                }
        }
    }

#pragma unroll
    for (int mi = 0; mi < 2; ++mi)
#pragma unroll
        for (int ni = 0; ni < 4; ++ni) {
            int row = bm + wm * 32 + mi * 16 + g;
            int col = bn + wn * 32 + ni * 8 + 2 * tg;
            float2 v0 = make_float2(c[mi][ni][0], c[mi][ni][1]);
            float2 v1 = make_float2(c[mi][ni][2], c[mi][ni][3]);
            *(float2*)&C[(size_t)row * ldc + col]       = v0;
            *(float2*)&C[(size_t)(row + 8) * ldc + col] = v1;
        }
}

// ---------------- GRU epilogue: combine gangs, nonlinearity, Hg ----------------
__global__ void gru_epi_kernel(const float* __restrict__ Wih,
                               const float* __restrict__ bih, const float* __restrict__ bhh,
                               const int* __restrict__ node_type, const int* __restrict__ pos,
                               int v, int has_agg)
{
    int h = blockIdx.x * 160 + threadIdx.x;
    if (h >= HS) return;
    int b = blockIdx.y;
    int nb = g_n[b];
    int nt = node_type[b * MAXN + v];
    int pv = pos[b * MAXN + v];

    float gr = 0.f, gz = 0.f, gn = 0.f, hin = 0.f;
    if (has_agg) {
        const float* GH = g_GEMM + (size_t)b * NG_GRU;
        gr = GH[h]; gz = GH[NPG + h]; gn = GH[2 * NPG + h];
        hin = g_Hin[(size_t)b * KP + h];
    }
    float gir = Wih[h * XDIM + nt]            + Wih[h * XDIM + NVT + pv]            + bih[h];
    float giz = Wih[(h + HS) * XDIM + nt]     + Wih[(h + HS) * XDIM + NVT + pv]     + bih[h + HS];
    float gin = Wih[(h + 2 * HS) * XDIM + nt] + Wih[(h + 2 * HS) * XDIM + NVT + pv] + bih[h + 2 * HS];

    float rg = sigm(gir + gr + bhh[h]);
    float zg = sigm(giz + gz + bhh[h + HS]);
    float ng = tanhf(gin + rg * (gn + bhh[h + 2 * HS]));
    float hv = (1.f - zg) * ng + zg * hin;
    hv = (v < nb) ? hv : 0.f;
    g_Hv[(size_t)b * KP + h] = hv;
    if (v == nb - 1) g_Hg[(size_t)b * HS + h] = hv;
}

// ---------------- gate epilogue: gated[v] = sigm(gate)*mapper, + fused Hin for step v+1 ----------
__global__ void gate_epi_kernel(const float* __restrict__ Wg, const float* __restrict__ bg,
                                const float* __restrict__ Wm,
                                const int* __restrict__ pos, int v)
{
    int j = blockIdx.x * 160 + threadIdx.x;
    if (j >= HS) return;
    int b = blockIdx.y;
    int pv = pos[b * MAXN + v];

    const float* GM = g_GEMM + (size_t)b * NG_GATE;
    float gg = sigm(GM[j] + bg[j] + Wg[(size_t)j * VS + HS + pv]);
    float mm = GM[NPG + j] + Wm[(size_t)j * VS + HS + pv];
    float gv = gg * mm;
    g_gated[((size_t)v * BSZ + b) * KP + j] = gv;

    // Hin for step v+1: sum over predecessor mask (own gated[v] still in register)
    unsigned mask = g_pmask[b * MAXN + (v + 1)];
    float s = 0.f;
    for (int u = 0; u < v; ++u)
        if ((mask >> u) & 1u) s += g_gated[((size_t)u * BSZ + b) * KP + j];
    if ((mask >> v) & 1u) s += gv;
    g_Hin[(size_t)b * KP + j] = s;
}

// ---------------- heads: mu / logvar over Hfull = [Hg, Hd] ----------------
__global__ void final_kernel(const float* __restrict__ Wmu, const float* __restrict__ bmu,
                             const float* __restrict__ Wlv, const float* __restrict__ blv,
                             float* __restrict__ out)
{
    __shared__ float sh[8][GS + 3];
    int b0 = blockIdx.x * 8;
    for (int idx = threadIdx.x; idx < 8 * HS; idx += blockDim.x) {
        int i = idx / HS, k = idx % HS;
        sh[i][k] = g_Hg[(size_t)(b0 + i) * HS + k];
    }
    for (int idx = threadIdx.x; idx < 8 * FEAT; idx += blockDim.x) {
        int i = idx / FEAT, f = idx % FEAT;
        sh[i][HS + f] = g_Hd[(b0 + i) * FEAT + f];
    }
    __syncthreads();
    int t = threadIdx.x;
    if (t < 2 * NZ) {
        int head = t / NZ;
        int o = t % NZ;
        const float* W = head ? Wlv : Wmu;
        float bias = head ? blv[o] : bmu[o];
        float acc[8];
#pragma unroll
        for (int i = 0; i < 8; ++i) acc[i] = 0.f;
        for (int k = 0; k < GS; ++k) {
            float wv = W[o * GS + k];
#pragma unroll
            for (int i = 0; i < 8; ++i) acc[i] += sh[i][k] * wv;
        }
#pragma unroll
        for (int i = 0; i < 8; ++i)
            out[(size_t)head * BSZ * NZ + (size_t)(b0 + i) * NZ + o] = acc[i] + bias;
    }
}

// ---------------- launch ----------------
extern "C" void kernel_launch(void* const* d_in, const int* in_sizes, int n_in,
                              void* d_out, int out_size)
{
    const int*   node_type = (const int*)  d_in[0];
    const int*   pos       = (const int*)  d_in[1];
    const int*   adj       = (const int*)  d_in[2];
    const int*   vcount    = (const int*)  d_in[3];
    const float* r         = (const float*)d_in[4];
    const float* c         = (const float*)d_in[5];
    const float* gm        = (const float*)d_in[6];
    const float* Wih       = (const float*)d_in[7];
    const float* Whh       = (const float*)d_in[8];
    const float* bih       = (const float*)d_in[9];
    const float* bhh       = (const float*)d_in[10];
    const float* Wg        = (const float*)d_in[11];
    const float* bg        = (const float*)d_in[12];
    const float* Wm        = (const float*)d_in[13];
    const float* W1        = (const float*)d_in[14];
    const float* b1        = (const float*)d_in[15];
    const float* W2        = (const float*)d_in[16];
    const float* b2        = (const float*)d_in[17];
    const float* Wmu       = (const float*)d_in[18];
    const float* bmu       = (const float*)d_in[19];
    const float* Wlv       = (const float*)d_in[20];
    const float* blv       = (const float*)d_in[21];
    float* out = (float*)d_out;

    // device-global pointers (host side must use symbols via kernels; pass via template of launches)
    setup_kernel<<<BSZ / 128, 128>>>(vcount, pos, adj, r, c, gm, W1, b1, W2, b2);
    pack_kernel<<<((NG_GRU + NG_GATE) * KP + 255) / 256, 256>>>(Whh, Wg, Wm);

    float* dHin;  cudaGetSymbolAddress((void**)&dHin,  g_Hin);
    float* dHv;   cudaGetSymbolAddress((void**)&dHv,   g_Hv);
    float* dGE;   cudaGetSymbolAddress((void**)&dGE,   g_GEMM);
    float* dWhhP; cudaGetSymbolAddress((void**)&dWhhP, g_Whh_p);
    float* dWgmP; cudaGetSymbolAddress((void**)&dWgmP, g_Wgm_p);

    dim3 grid_gru (BSZ / 128, NG_GRU  / 64);   // (32, 15)
    dim3 grid_gate(BSZ / 128, NG_GATE / 64);   // (32, 10)
    dim3 epi_grid(2, BSZ);

    for (int v = 0; v < MAXN; ++v) {
        if (v > 0) {
            gemm_tf32<<<grid_gru, 256>>>(dHin, dWhhP, dGE, NG_GRU);
        }
        gru_epi_kernel<<<epi_grid, 160>>>(Wih, bih, bhh, node_type, pos, v, v > 0 ? 1 : 0);
        if (v < MAXN - 1) {
            gemm_tf32<<<grid_gate, 256>>>(dHv, dWgmP, dGE, NG_GATE);
            gate_epi_kernel<<<epi_grid, 160>>>(Wg, bg, Wm, pos, v);
        }
    }
    final_kernel<<<BSZ / 8, 128>>>(Wmu, bmu, Wlv, blv, out);
}

// round 4
// speedup vs baseline: 3.0997x; 1.4626x over previous
#include <cuda_runtime.h>
#include <cstdint>

// ---------------- problem constants ----------------
#define BSZ   4096
#define MAXN  10
#define NVT   26
#define MAXPOS 9
#define HS    301
#define NZ    56
#define EMB   16
#define FEAT  8
#define VS    310
#define XDIM  35
#define DFD   27
#define GS    309
#define KP    304        // K padded (19*16)
#define NPG   320        // per-gang N padded
#define NG_GRU  (3*NPG)
#define NG_GATE (2*NPG)
#define NT    19         // K tiles of 16
#define NCID  (NVT*MAXPOS)   // 234

#define GRU_SMEM_BYTES ((2*128*20 + 2*192*20) * 4)   // 51200

// ---------------- device scratch (zero-initialized; pads kept zero) ----------------
__device__ float g_gated[(size_t)8 * BSZ * KP];   // gate steps v=0..7 (sorted rows)
__device__ float g_Hin[(size_t)BSZ * KP];
__device__ float g_Hv [(size_t)BSZ * KP];
__device__ float g_Hg [(size_t)BSZ * HS];
__device__ float g_Hd [(size_t)BSZ * FEAT];
__device__ int   g_n   [BSZ];
__device__ int   g_perm[BSZ];                     // sorted (desc nb) -> orig b
__device__ int   g_nbs [BSZ];                     // nb in sorted order
__device__ int   g_cnt [MAXN + 1];                // cnt[v] = #{nb > v}
__device__ int   g_cid [BSZ * MAXN];              // nt*9+pv per (orig b, v)
__device__ unsigned g_pmask[BSZ * MAXN];
__device__ float g_Whh_p[(size_t)NG_GRU  * KP];   // tf32-rounded packed Whh
__device__ float g_Wgm_p[(size_t)NG_GATE * KP];   // tf32-rounded packed Wg|Wm
__device__ float g_GI   [(size_t)NCID * 3 * KP];  // gi table (bih, bhh_r/z folded)
__device__ float g_gateb[9 * KP];                 // bg + Wg[:,HS+p]
__device__ float g_mapb [9 * KP];                 // Wm[:,HS+p]

__device__ __forceinline__ float sigm(float x) { return 1.f / (1.f + __expf(-x)); }
__device__ __forceinline__ float f2tf(float x) {
    uint32_t r; asm("cvt.rna.tf32.f32 %0, %1;" : "=r"(r) : "f"(x)); return __uint_as_float(r);
}
__device__ __forceinline__ void cp16(uint32_t dst, const float* src) {
    asm volatile("cp.async.cg.shared.global [%0], [%1], 16;" :: "r"(dst), "l"(src));
}
#define CP_COMMIT asm volatile("cp.async.commit_group;")
#define CP_WAIT1  asm volatile("cp.async.wait_group 1;")
#define CP_WAIT0  asm volatile("cp.async.wait_group 0;")

#define MMA_TF32(C, A, B)                                                     \
    asm volatile(                                                             \
        "mma.sync.aligned.m16n8k8.row.col.f32.tf32.tf32.f32 "                 \
        "{%0,%1,%2,%3}, {%4,%5,%6,%7}, {%8,%9}, {%0,%1,%2,%3};"               \
        : "+f"((C)[0]), "+f"((C)[1]), "+f"((C)[2]), "+f"((C)[3])              \
        : "r"((A)[0]), "r"((A)[1]), "r"((A)[2]), "r"((A)[3]),                 \
          "r"((B)[0]), "r"((B)[1]))

// ---------------- setup: nb, pmask, cid, df MLP ----------------
__global__ void setup_kernel(const int* __restrict__ vc, const int* __restrict__ node_type,
                             const int* __restrict__ pos, const int* __restrict__ adj,
                             const float* __restrict__ r, const float* __restrict__ c_,
                             const float* __restrict__ gm,
                             const float* __restrict__ W1, const float* __restrict__ b1,
                             const float* __restrict__ W2, const float* __restrict__ b2)
{
    int b = blockIdx.x * blockDim.x + threadIdx.x;
    if (b >= BSZ) return;
    int nb = vc[b]; nb = nb < 1 ? 1 : (nb > MAXN ? MAXN : nb);
    g_n[b] = nb;

    for (int v = 0; v < MAXN; ++v) {
        unsigned m = 0;
        if (v < nb)
            for (int u = 0; u < v; ++u)
                if (adj[(size_t)b * 100 + u * 10 + v]) m |= 1u << u;
        g_pmask[b * MAXN + v] = m;
        g_cid[b * MAXN + v] = node_type[b * MAXN + v] * MAXPOS + pos[b * MAXN + v];
    }

    float df[DFD];
#pragma unroll
    for (int d = 0; d < DFD; ++d) df[d] = 0.f;
    for (int v = 0; v < MAXN; ++v) {
        if (v < nb) {
            int p = pos[b * MAXN + v] * 3;
            df[p]     = r [b * MAXN + v];
            df[p + 1] = c_[b * MAXN + v];
            df[p + 2] = gm[b * MAXN + v];
        }
    }
    float t16[EMB];
#pragma unroll
    for (int e = 0; e < EMB; ++e) {
        float s = b1[e];
#pragma unroll
        for (int d = 0; d < DFD; ++d) s += df[d] * W1[e * DFD + d];
        t16[e] = fmaxf(s, 0.f);
    }
#pragma unroll
    for (int f = 0; f < FEAT; ++f) {
        float s = b2[f];
#pragma unroll
        for (int e = 0; e < EMB; ++e) s += t16[e] * W2[f * EMB + e];
        g_Hd[b * FEAT + f] = s;
    }
}

// ---------------- counting sort by nb (descending) ----------------
__global__ void sort_kernel()
{
    __shared__ int cnt_s[16], start_s[16], cur_s[16];
    int tid = threadIdx.x;
    if (tid < 16) cnt_s[tid] = 0;
    __syncthreads();
    for (int b = tid; b < BSZ; b += blockDim.x) atomicAdd(&cnt_s[g_n[b]], 1);
    __syncthreads();
    if (tid == 0) {
        int run = 0;
        for (int k = MAXN; k >= 1; --k) { start_s[k] = run; run += cnt_s[k]; }
        for (int v = 0; v <= MAXN; ++v) {
            int s = 0;
            for (int k = v + 1; k <= MAXN; ++k) s += cnt_s[k];
            g_cnt[v] = s;
        }
        for (int k = 1; k <= MAXN; ++k) cur_s[k] = start_s[k];
    }
    __syncthreads();
    for (int b = tid; b < BSZ; b += blockDim.x) {
        int k = g_n[b];
        int idx = atomicAdd(&cur_s[k], 1);
        g_perm[idx] = b;
        g_nbs[idx] = k;
    }
}

// ---------------- GI table: per (nt,pv) combo, gi + bih (+ bhh for r,z) ----------------
__global__ void gi_kernel(const float* __restrict__ Wih, const float* __restrict__ bih,
                          const float* __restrict__ bhh)
{
    int cid = blockIdx.x;
    int t = cid / MAXPOS, p = cid % MAXPOS;
    for (int idx = threadIdx.x; idx < 3 * KP; idx += blockDim.x) {
        int gg = idx / KP, h = idx % KP;
        float v = 0.f;
        if (h < HS) {
            int row = gg * HS + h;
            v = Wih[row * XDIM + t] + Wih[row * XDIM + NVT + p] + bih[row];
            if (gg < 2) v += bhh[row];
        }
        g_GI[(size_t)cid * 3 * KP + idx] = v;
    }
}

// ---------------- pack: tf32-rounded padded weights + gate pos tables ----------------
__global__ void pack_kernel(const float* __restrict__ Whh,
                            const float* __restrict__ Wg, const float* __restrict__ bg,
                            const float* __restrict__ Wm)
{
    int idx = blockIdx.x * blockDim.x + threadIdx.x;
    const int tot1 = NG_GRU * KP, tot2 = NG_GATE * KP, tot3 = 9 * KP;
    if (idx < tot1) {
        int row = idx / KP, k = idx % KP;
        int gg = row / NPG, n = row % NPG;
        float v = 0.f;
        if (n < HS && k < HS) v = f2tf(Whh[(size_t)(gg * HS + n) * HS + k]);
        g_Whh_p[idx] = v;
    } else if (idx < tot1 + tot2) {
        int j = idx - tot1;
        int row = j / KP, k = j % KP;
        int gg = row / NPG, n = row % NPG;
        const float* src = gg ? Wm : Wg;
        float v = 0.f;
        if (n < HS && k < HS) v = f2tf(src[(size_t)n * VS + k]);
        g_Wgm_p[j] = v;
    } else if (idx < tot1 + tot2 + tot3) {
        int j = idx - tot1 - tot2;
        int p = j / KP, h = j % KP;
        g_gateb[j] = (h < HS) ? bg[h] + Wg[(size_t)h * VS + HS + p] : 0.f;
    } else if (idx < tot1 + tot2 + 2 * tot3) {
        int j = idx - tot1 - tot2 - tot3;
        int p = j / KP, h = j % KP;
        g_mapb[j] = (h < HS) ? Wm[(size_t)h * VS + HS + p] : 0.f;
    }
}

// ================= fused GRU step: 3-gang tf32 GEMM + GRU nonlinearity =================
// BM=128, BN=64 per gang, BK=16, 8 warps (4m x 2n); dynamic smem (51200 B)
__global__ void __launch_bounds__(256) gru_fused(const float* __restrict__ bhh,
                                                 int v, int has_agg)
{
    const int tid = threadIdx.x, warp = tid >> 5, lane = tid & 31;
    const int wm = warp & 3, wn = warp >> 2, g = lane >> 2, tg = lane & 3;
    const int bm = blockIdx.x * 128, bn = blockIdx.y * 64;
    const int cntv = g_cnt[v];
    if (bm >= cntv) return;

    extern __shared__ float smem[];
    // As: [2][128][20]  Bs: [2][192][20]
    float (*As)[128][20] = (float (*)[128][20])smem;
    float (*Bs)[192][20] = (float (*)[192][20])(smem + 2 * 128 * 20);

    float acc[3][2][4][4];
#pragma unroll
    for (int gg = 0; gg < 3; ++gg)
#pragma unroll
        for (int mi = 0; mi < 2; ++mi)
#pragma unroll
            for (int ni = 0; ni < 4; ++ni)
#pragma unroll
                for (int q = 0; q < 4; ++q) acc[gg][mi][ni][q] = 0.f;

    if (has_agg) {
        const uint32_t sA = (uint32_t)__cvta_generic_to_shared(&As[0][0][0]);
        const uint32_t sB = (uint32_t)__cvta_generic_to_shared(&Bs[0][0][0]);
        const float* Ag = g_Hin;
        const float* Bg = g_Whh_p;
        const int arow = tid >> 2, acol = (tid & 3) << 2;
        {
#pragma unroll
            for (int t = 0; t < 2; ++t) {
                int row = arow + t * 64;
                cp16(sA + (row * 20 + acol) * 4, Ag + (size_t)(bm + row) * KP + acol);
            }
#pragma unroll
            for (int t = 0; t < 3; ++t) {
                int row = arow + t * 64;
                int gg = row >> 6, n = row & 63;
                cp16(sB + (row * 20 + acol) * 4, Bg + (size_t)(gg * NPG + bn + n) * KP + acol);
            }
            CP_COMMIT;
        }
        for (int kt = 0; kt < NT; ++kt) {
            int cur = kt & 1;
            __syncthreads();
            if (kt + 1 < NT) {
                int nxt = cur ^ 1;
                int k0 = (kt + 1) * 16;
#pragma unroll
                for (int t = 0; t < 2; ++t) {
                    int row = arow + t * 64;
                    cp16(sA + (nxt * 2560 + row * 20 + acol) * 4,
                         Ag + (size_t)(bm + row) * KP + k0 + acol);
                }
#pragma unroll
                for (int t = 0; t < 3; ++t) {
                    int row = arow + t * 64;
                    int gg = row >> 6, n = row & 63;
                    cp16(sB + (nxt * 3840 + row * 20 + acol) * 4,
                         Bg + (size_t)(gg * NPG + bn + n) * KP + k0 + acol);
                }
                CP_COMMIT; CP_WAIT1;
            } else {
                CP_WAIT0;
            }
            __syncthreads();
#pragma unroll
            for (int ks = 0; ks < 2; ++ks) {
                const int k0 = ks * 8;
                uint32_t af[2][4];
#pragma unroll
                for (int mi = 0; mi < 2; ++mi) {
                    int rb = wm * 32 + mi * 16;
                    af[mi][0] = __float_as_uint(As[cur][rb + g    ][k0 + tg]);
                    af[mi][1] = __float_as_uint(As[cur][rb + g + 8][k0 + tg]);
                    af[mi][2] = __float_as_uint(As[cur][rb + g    ][k0 + tg + 4]);
                    af[mi][3] = __float_as_uint(As[cur][rb + g + 8][k0 + tg + 4]);
                }
                uint32_t bf[3][4][2];
#pragma unroll
                for (int gg = 0; gg < 3; ++gg)
#pragma unroll
                    for (int ni = 0; ni < 4; ++ni) {
                        int row = gg * 64 + wn * 32 + ni * 8 + g;
                        bf[gg][ni][0] = __float_as_uint(Bs[cur][row][k0 + tg]);
                        bf[gg][ni][1] = __float_as_uint(Bs[cur][row][k0 + tg + 4]);
                    }
#pragma unroll
                for (int gg = 0; gg < 3; ++gg)
#pragma unroll
                    for (int mi = 0; mi < 2; ++mi)
#pragma unroll
                        for (int ni = 0; ni < 4; ++ni)
                            MMA_TF32(acc[gg][mi][ni], af[mi], bf[gg][ni]);
            }
        }
    }

    // ---- fused GRU epilogue ----
#pragma unroll
    for (int mi = 0; mi < 2; ++mi) {
#pragma unroll
        for (int rr = 0; rr < 2; ++rr) {
            int i = bm + wm * 32 + mi * 16 + g + rr * 8;
            int orig = g_perm[i];
            int cid  = g_cid[orig * MAXN + v];
            int nbi  = g_nbs[i];
            bool valid = (i < cntv);
            const float* GIrow = g_GI + (size_t)cid * 3 * KP;
            int q0 = 2 * rr, q1 = 2 * rr + 1;
#pragma unroll
            for (int ni = 0; ni < 4; ++ni) {
                int j = bn + wn * 32 + ni * 8 + 2 * tg;
                if (j >= HS) continue;
                float2 GIr = *(const float2*)(GIrow + j);
                float2 GIz = *(const float2*)(GIrow + KP + j);
                float2 GIn = *(const float2*)(GIrow + 2 * KP + j);
                float bn0 = bhh[2 * HS + j];
                float bn1 = (j + 1 < HS) ? bhh[2 * HS + j + 1] : 0.f;
                float hin0 = 0.f, hin1 = 0.f;
                if (has_agg) {
                    float2 t = *(const float2*)(g_Hin + (size_t)i * KP + j);
                    hin0 = t.x; hin1 = t.y;
                }
                float rg0 = sigm(GIr.x + acc[0][mi][ni][q0]);
                float zg0 = sigm(GIz.x + acc[1][mi][ni][q0]);
                float ng0 = tanhf(GIn.x + rg0 * (acc[2][mi][ni][q0] + bn0));
                float hv0 = (1.f - zg0) * ng0 + zg0 * hin0;
                float rg1 = sigm(GIr.y + acc[0][mi][ni][q1]);
                float zg1 = sigm(GIz.y + acc[1][mi][ni][q1]);
                float ng1 = tanhf(GIn.y + rg1 * (acc[2][mi][ni][q1] + bn1));
                float hv1 = (1.f - zg1) * ng1 + zg1 * hin1;
                if (!valid) { hv0 = 0.f; hv1 = 0.f; }
                if (j + 1 >= HS) hv1 = 0.f;
                *(float2*)(g_Hv + (size_t)i * KP + j) = make_float2(f2tf(hv0), f2tf(hv1));
                if (valid && v == nbi - 1) {
                    g_Hg[(size_t)orig * HS + j] = hv0;
                    if (j + 1 < HS) g_Hg[(size_t)orig * HS + j + 1] = hv1;
                }
            }
        }
    }
}

// ================= fused gate step: 2-gang GEMM + sigm*map + Hin(v+1) =================
__global__ void __launch_bounds__(256) gate_fused(int v)
{
    const int tid = threadIdx.x, warp = tid >> 5, lane = tid & 31;
    const int wm = warp & 3, wn = warp >> 2, g = lane >> 2, tg = lane & 3;
    const int bm = blockIdx.x * 128, bn = blockIdx.y * 64;
    const int cntv = g_cnt[v + 1];
    if (bm >= cntv) return;

    __shared__ float As[2][128][20];
    __shared__ float Bs[2][128][20];

    float acc[2][2][4][4];
#pragma unroll
    for (int gg = 0; gg < 2; ++gg)
#pragma unroll
        for (int mi = 0; mi < 2; ++mi)
#pragma unroll
            for (int ni = 0; ni < 4; ++ni)
#pragma unroll
                for (int q = 0; q < 4; ++q) acc[gg][mi][ni][q] = 0.f;

    {
        const uint32_t sA = (uint32_t)__cvta_generic_to_shared(&As[0][0][0]);
        const uint32_t sB = (uint32_t)__cvta_generic_to_shared(&Bs[0][0][0]);
        const float* Ag = g_Hv;
        const float* Bg = g_Wgm_p;
        const int arow = tid >> 2, acol = (tid & 3) << 2;
        {
#pragma unroll
            for (int t = 0; t < 2; ++t) {
                int row = arow + t * 64;
                cp16(sA + (row * 20 + acol) * 4, Ag + (size_t)(bm + row) * KP + acol);
            }
#pragma unroll
            for (int t = 0; t < 2; ++t) {
                int row = arow + t * 64;
                int gg = row >> 6, n = row & 63;
                cp16(sB + (row * 20 + acol) * 4, Bg + (size_t)(gg * NPG + bn + n) * KP + acol);
            }
            CP_COMMIT;
        }
        for (int kt = 0; kt < NT; ++kt) {
            int cur = kt & 1;
            __syncthreads();
            if (kt + 1 < NT) {
                int nxt = cur ^ 1;
                int k0 = (kt + 1) * 16;
#pragma unroll
                for (int t = 0; t < 2; ++t) {
                    int row = arow + t * 64;
                    cp16(sA + (nxt * 2560 + row * 20 + acol) * 4,
                         Ag + (size_t)(bm + row) * KP + k0 + acol);
                }
#pragma unroll
                for (int t = 0; t < 2; ++t) {
                    int row = arow + t * 64;
                    int gg = row >> 6, n = row & 63;
                    cp16(sB + (nxt * 2560 + row * 20 + acol) * 4,
                         Bg + (size_t)(gg * NPG + bn + n) * KP + k0 + acol);
                }
                CP_COMMIT; CP_WAIT1;
            } else {
                CP_WAIT0;
            }
            __syncthreads();
#pragma unroll
            for (int ks = 0; ks < 2; ++ks) {
                const int k0 = ks * 8;
                uint32_t af[2][4];
#pragma unroll
                for (int mi = 0; mi < 2; ++mi) {
                    int rb = wm * 32 + mi * 16;
                    af[mi][0] = __float_as_uint(As[cur][rb + g    ][k0 + tg]);
                    af[mi][1] = __float_as_uint(As[cur][rb + g + 8][k0 + tg]);
                    af[mi][2] = __float_as_uint(As[cur][rb + g    ][k0 + tg + 4]);
                    af[mi][3] = __float_as_uint(As[cur][rb + g + 8][k0 + tg + 4]);
                }
                uint32_t bf[2][4][2];
#pragma unroll
                for (int gg = 0; gg < 2; ++gg)
#pragma unroll
                    for (int ni = 0; ni < 4; ++ni) {
                        int row = gg * 64 + wn * 32 + ni * 8 + g;
                        bf[gg][ni][0] = __float_as_uint(Bs[cur][row][k0 + tg]);
                        bf[gg][ni][1] = __float_as_uint(Bs[cur][row][k0 + tg + 4]);
                    }
#pragma unroll
                for (int gg = 0; gg < 2; ++gg)
#pragma unroll
                    for (int mi = 0; mi < 2; ++mi)
#pragma unroll
                        for (int ni = 0; ni < 4; ++ni)
                            MMA_TF32(acc[gg][mi][ni], af[mi], bf[gg][ni]);
            }
        }
    }

    // ---- fused gate epilogue + Hin(v+1) ----
#pragma unroll
    for (int mi = 0; mi < 2; ++mi) {
#pragma unroll
        for (int rr = 0; rr < 2; ++rr) {
            int i = bm + wm * 32 + mi * 16 + g + rr * 8;
            int orig = g_perm[i];
            int pv = g_cid[orig * MAXN + v] % MAXPOS;
            unsigned mask = g_pmask[orig * MAXN + v + 1];
            int q0 = 2 * rr, q1 = 2 * rr + 1;
#pragma unroll
            for (int ni = 0; ni < 4; ++ni) {
                int j = bn + wn * 32 + ni * 8 + 2 * tg;
                if (j >= HS) continue;
                float2 gb = *(const float2*)(g_gateb + pv * KP + j);
                float2 mb = *(const float2*)(g_mapb + pv * KP + j);
                float gv0 = sigm(acc[0][mi][ni][q0] + gb.x) * (acc[1][mi][ni][q0] + mb.x);
                float gv1 = sigm(acc[0][mi][ni][q1] + gb.y) * (acc[1][mi][ni][q1] + mb.y);
                if (j + 1 >= HS) gv1 = 0.f;
                *(float2*)(g_gated + ((size_t)v * BSZ + i) * KP + j) = make_float2(gv0, gv1);
                float s0 = 0.f, s1 = 0.f;
                for (int u = 0; u < v; ++u)
                    if ((mask >> u) & 1u) {
                        float2 t = *(const float2*)(g_gated + ((size_t)u * BSZ + i) * KP + j);
                        s0 += t.x; s1 += t.y;
                    }
                if ((mask >> v) & 1u) { s0 += gv0; s1 += gv1; }
                *(float2*)(g_Hin + (size_t)i * KP + j) = make_float2(f2tf(s0), f2tf(s1));
            }
        }
    }
}

// ---------------- heads ----------------
__global__ void final_kernel(const float* __restrict__ Wmu, const float* __restrict__ bmu,
                             const float* __restrict__ Wlv, const float* __restrict__ blv,
                             float* __restrict__ out)
{
    __shared__ float sh[8][GS + 3];
    int b0 = blockIdx.x * 8;
    for (int idx = threadIdx.x; idx < 8 * HS; idx += blockDim.x) {
        int i = idx / HS, k = idx % HS;
        sh[i][k] = g_Hg[(size_t)(b0 + i) * HS + k];
    }
    for (int idx = threadIdx.x; idx < 8 * FEAT; idx += blockDim.x) {
        int i = idx / FEAT, f = idx % FEAT;
        sh[i][HS + f] = g_Hd[(b0 + i) * FEAT + f];
    }
    __syncthreads();
    int t = threadIdx.x;
    if (t < 2 * NZ) {
        int head = t / NZ;
        int o = t % NZ;
        const float* W = head ? Wlv : Wmu;
        float bias = head ? blv[o] : bmu[o];
        float acc[8];
#pragma unroll
        for (int i = 0; i < 8; ++i) acc[i] = 0.f;
        for (int k = 0; k < GS; ++k) {
            float wv = W[o * GS + k];
#pragma unroll
            for (int i = 0; i < 8; ++i) acc[i] += sh[i][k] * wv;
        }
#pragma unroll
        for (int i = 0; i < 8; ++i)
            out[(size_t)head * BSZ * NZ + (size_t)(b0 + i) * NZ + o] = acc[i] + bias;
    }
}

// ---------------- launch ----------------
extern "C" void kernel_launch(void* const* d_in, const int* in_sizes, int n_in,
                              void* d_out, int out_size)
{
    const int*   node_type = (const int*)  d_in[0];
    const int*   pos       = (const int*)  d_in[1];
    const int*   adj       = (const int*)  d_in[2];
    const int*   vcount    = (const int*)  d_in[3];
    const float* r         = (const float*)d_in[4];
    const float* c         = (const float*)d_in[5];
    const float* gm        = (const float*)d_in[6];
    const float* Wih       = (const float*)d_in[7];
    const float* Whh       = (const float*)d_in[8];
    const float* bih       = (const float*)d_in[9];
    const float* bhh       = (const float*)d_in[10];
    const float* Wg        = (const float*)d_in[11];
    const float* bg        = (const float*)d_in[12];
    const float* Wm        = (const float*)d_in[13];
    const float* W1        = (const float*)d_in[14];
    const float* b1        = (const float*)d_in[15];
    const float* W2        = (const float*)d_in[16];
    const float* b2        = (const float*)d_in[17];
    const float* Wmu       = (const float*)d_in[18];
    const float* bmu       = (const float*)d_in[19];
    const float* Wlv       = (const float*)d_in[20];
    const float* blv       = (const float*)d_in[21];
    float* out = (float*)d_out;

    cudaFuncSetAttribute(gru_fused, cudaFuncAttributeMaxDynamicSharedMemorySize,
                         GRU_SMEM_BYTES);

    setup_kernel<<<BSZ / 128, 128>>>(vcount, node_type, pos, adj, r, c, gm, W1, b1, W2, b2);
    sort_kernel<<<1, 1024>>>();
    gi_kernel<<<NCID, 256>>>(Wih, bih, bhh);
    {
        int tot = NG_GRU * KP + NG_GATE * KP + 2 * 9 * KP;
        pack_kernel<<<(tot + 255) / 256, 256>>>(Whh, Wg, bg, Wm);
    }

    dim3 grid(32, 5);
    gru_fused<<<grid, 256, GRU_SMEM_BYTES>>>(bhh, 0, 0);
    for (int v = 0; v < 8; ++v) {
        gate_fused<<<grid, 256>>>(v);
        gru_fused<<<grid, 256, GRU_SMEM_BYTES>>>(bhh, v + 1, 1);
    }
    final_kernel<<<BSZ / 8, 128>>>(Wmu, bmu, Wlv, blv, out);
}